// round 15
// baseline (speedup 1.0000x reference)
#include <cuda_runtime.h>
#include <cuda_bf16.h>
#include <cuda_fp16.h>
#include <cstdint>

// Problem constants
#define BB 8
#define CC 256
#define HH 128
#define WW 128
#define ND 64

// ---------------------------------------------------------------------------
// Scratch (__device__ globals; no runtime allocation)
// ---------------------------------------------------------------------------
__device__ float g_style[BB * CC];
__device__ __align__(256) __half g_Af[BB * 9 * CC * CC];            // [b][tap][oc][i]
__device__ __align__(256) __half g_Ff[(size_t)BB * HH * WW * CC];   // [b][y][x][c]

// ---------------------------------------------------------------------------
// PTX helpers (sm_80-era; compile on compute_103)
// ---------------------------------------------------------------------------
__device__ __forceinline__ uint32_t smem_u32(const void* p) {
    uint32_t a;
    asm("{ .reg .u64 t; cvta.to.shared.u64 t, %1; cvt.u32.u64 %0, t; }" : "=r"(a) : "l"(p));
    return a;
}
__device__ __forceinline__ void cpa16(uint32_t dst, const void* src, uint32_t bytes) {
    asm volatile("cp.async.cg.shared.global [%0], [%1], 16, %2;"
                 :: "r"(dst), "l"(src), "r"(bytes) : "memory");
}
__device__ __forceinline__ void cpa_mbar_arrive(uint32_t mbar) {
    asm volatile("cp.async.mbarrier.arrive.noinc.shared::cta.b64 [%0];"
                 :: "r"(mbar) : "memory");
}
#define MBARRIER_INIT(a, c) \
    asm volatile("mbarrier.init.shared.b64 [%0], %1;" :: "r"((uint32_t)(a)), "r"((uint32_t)(c)) : "memory")
#define MBARRIER_ARRIVE(a) \
    asm volatile("mbarrier.arrive.shared.b64 _, [%0];" :: "r"((uint32_t)(a)) : "memory")
#define MBARRIER_WAIT_PARITY(a, ph) do { \
    uint32_t _m = (uint32_t)(a); uint32_t _p = (uint32_t)(ph); uint32_t _d; \
    asm volatile("{\n .reg .pred p;\n mbarrier.try_wait.parity.acquire.cta.shared::cta.b64 p, [%1], %2;\n selp.b32 %0,1,0,p;\n}" \
        : "=r"(_d) : "r"(_m), "r"(_p) : "memory"); \
    if (!_d) { \
        asm volatile("{\n .reg .pred P1;\nWL_%=:\n mbarrier.try_wait.parity.acquire.cta.shared::cta.b64 P1, [%0], %1, 0x989680;\n @P1 bra.uni WD_%=;\n bra.uni WL_%=;\nWD_%=:\n}" \
            :: "r"(_m), "r"(_p) : "memory"); \
    } } while (0)

__device__ __forceinline__ uint32_t swz(uint32_t off) { return off ^ ((off >> 3) & 0x70); }

__device__ __forceinline__ void ldsm_x4(uint32_t& r0, uint32_t& r1, uint32_t& r2, uint32_t& r3,
                                        uint32_t addr) {
    asm volatile("ldmatrix.sync.aligned.m8n8.x4.shared.b16 {%0,%1,%2,%3}, [%4];"
                 : "=r"(r0), "=r"(r1), "=r"(r2), "=r"(r3) : "r"(addr));
}
__device__ __forceinline__ void mma_fp16(float* d, const uint32_t* a, const uint32_t* b) {
    asm volatile(
        "mma.sync.aligned.m16n8k16.row.col.f32.f16.f16.f32 "
        "{%0,%1,%2,%3}, {%4,%5,%6,%7}, {%8,%9}, {%0,%1,%2,%3};"
        : "+f"(d[0]), "+f"(d[1]), "+f"(d[2]), "+f"(d[3])
        : "r"(a[0]), "r"(a[1]), "r"(a[2]), "r"(a[3]), "r"(b[0]), "r"(b[1]));
}

// ---------------------------------------------------------------------------
// Kernel 0: style
// ---------------------------------------------------------------------------
__global__ void style_kernel(const float* __restrict__ nf,
                             const float* __restrict__ mw,
                             const float* __restrict__ mb) {
    int b = blockIdx.x, c = threadIdx.x;
    const float* nfb = nf + b * ND;
    const float* mwc = mw + c * ND;
    float s = 0.f;
#pragma unroll
    for (int d = 0; d < ND; ++d) s += nfb[d] * mwc[d];
    g_style[b * CC + c] = s + mb[c];
}

// ---------------------------------------------------------------------------
// Kernel 1: modulate + demod weights -> fp16, layout [b][tap][oc][i]
// ---------------------------------------------------------------------------
__global__ void modw_kernel(const float* __restrict__ weight) {
    int o = blockIdx.x, b = blockIdx.y, i = threadIdx.x;
    const float scale = 1.0f / 48.0f;
    float s = g_style[b * CC + i] * scale;
    const float* wp = weight + (o * CC + i) * 9;
    float v[9];
    float sq = 0.f;
#pragma unroll
    for (int k = 0; k < 9; ++k) { v[k] = wp[k] * s; sq += v[k] * v[k]; }

    __shared__ float red[8];
#pragma unroll
    for (int off = 16; off; off >>= 1) sq += __shfl_xor_sync(0xffffffffu, sq, off);
    if ((threadIdx.x & 31) == 0) red[threadIdx.x >> 5] = sq;
    __syncthreads();
    if (threadIdx.x < 8) {
        float t = red[threadIdx.x];
#pragma unroll
        for (int off = 4; off; off >>= 1) t += __shfl_xor_sync(0xffu, t, off);
        if (threadIdx.x == 0) red[0] = t;
    }
    __syncthreads();
    float demod = rsqrtf(red[0] + 1e-8f);
#pragma unroll
    for (int k = 0; k < 9; ++k) {
        size_t idx = ((size_t)((b * 9 + k) * CC) + o) * CC + i;
        g_Af[idx] = __float2half(v[k] * demod);
    }
}

// ---------------------------------------------------------------------------
// Kernel 2: fea NCHW -> [b][y][x][c] fp16
// ---------------------------------------------------------------------------
__global__ __launch_bounds__(256)
void tsplit_kernel(const float* __restrict__ fea) {
    int y = blockIdx.x, b = blockIdx.y;
    __shared__ float t[64][129];
    for (int cc = 0; cc < 4; ++cc) {
#pragma unroll
        for (int k = 0; k < 32; ++k) {
            int idx = threadIdx.x + k * 256;
            int cs = idx >> 7, x = idx & 127;
            t[cs][x] = fea[(((size_t)(b * CC + cc * 64 + cs)) * HH + y) * WW + x];
        }
        __syncthreads();
#pragma unroll
        for (int k = 0; k < 32; ++k) {
            int idx = threadIdx.x + k * 256;
            int c2 = idx & 63, x = idx >> 6;
            size_t o = ((size_t)((b * HH + y) * WW + x)) * CC + cc * 64 + c2;
            g_Ff[o] = __float2half(t[c2][x]);
        }
        __syncthreads();
    }
}

// ---------------------------------------------------------------------------
// Kernel 3: WARP-SPECIALIZED implicit-GEMM conv via mma.sync (fp16, f32 acc).
// grid (y=128, mt=2, b=8) = 2048 CTAs; CTA = 128 oc x 128 px; 160 threads:
//   warps 0-3 consumers (2M x 2N, warp tile 64x64), warp 4 producer.
// 36 K-steps (9 taps x 4 chunks of 64 ch); 3-stage ring of 32KB.
// full[s]: count=32, flipped by cp.async.mbarrier.arrive from producer lanes.
// empty[s]: count=4, one mbarrier.arrive per consumer warp (lane 0).
// Consumers have NO __syncthreads and NO cp.async in their loop.
// 2 CTAs per SM (192.3KB smem) -> 2 consumer warps per SMSP.
// ---------------------------------------------------------------------------
#define NSTAGE 3
#define STAGE_BYTES 32768
#define DATA_BYTES (NSTAGE * STAGE_BYTES)
#define SMEM_TOTAL (DATA_BYTES + 128)

__global__ __launch_bounds__(160, 2)
void gemm_kernel(float* __restrict__ out) {
    extern __shared__ char smem[];
    const uint32_t sb = smem_u32(smem);
    const int tid  = threadIdx.x;
    const int lane = tid & 31;
    const int wid  = tid >> 5;
    const int y = blockIdx.x, mt = blockIdx.y, b = blockIdx.z;

    const uint32_t barBase = sb + DATA_BYTES;
    // full[s] @ barBase+16s ; empty[s] @ barBase+16s+8
    if (tid == 0) {
#pragma unroll
        for (int s = 0; s < NSTAGE; ++s) {
            MBARRIER_INIT(barBase + 16 * s, 32);      // full: 32 producer lanes
            MBARRIER_INIT(barBase + 16 * s + 8, 4);   // empty: 4 consumer warps
        }
    }
    __syncthreads();   // barrier init visible to all warps (only sync in kernel)

    if (wid == 4) {
        // ======================= PRODUCER WARP =======================
        const int aR0 = lane * 4;                    // 4 A rows per lane
        const int bR0 = lane * 4;                    // 4 B rows per lane
        const size_t aBase = ((size_t)(b * 9) * CC + mt * 128 + aR0) * CC;
        int st = 0, ph = 1;                          // phase=1: first waits pass
#pragma unroll 1
        for (int s = 0; s < 36; ++s) {
            const int tap = s >> 2, ck = s & 3;
            MBARRIER_WAIT_PARITY(barBase + 16 * st + 8, ph);   // wait empty
            const uint32_t stg = sb + (uint32_t)st * STAGE_BYTES;
            // A: 4 rows x 128B
            const __half* srcA = g_Af + aBase + (size_t)tap * CC * CC + ck * 64;
#pragma unroll
            for (int r = 0; r < 4; ++r)
#pragma unroll
                for (int j = 0; j < 8; ++j)
                    cpa16(stg + swz((uint32_t)(aR0 + r) * 128u + j * 16u),
                          srcA + (size_t)r * CC + j * 8, 16u);
            // B: 4 rows x 128B (zero-fill out-of-bounds via src-size 0)
            const int yy = y + tap / 3 - 1;
            const bool yv = (yy >= 0 && yy < HH);
#pragma unroll
            for (int r = 0; r < 4; ++r) {
                const int xx = bR0 + r + tap % 3 - 1;
                const bool bv = yv && xx >= 0 && xx < WW;
                const __half* srcB = g_Ff
                    + ((size_t)((b * HH + (bv ? yy : 0)) * WW + (bv ? xx : 0))) * CC + ck * 64;
                const uint32_t bsz = bv ? 16u : 0u;
#pragma unroll
                for (int j = 0; j < 8; ++j)
                    cpa16(stg + 16384u + swz((uint32_t)(bR0 + r) * 128u + j * 16u),
                          srcB + j * 8, bsz);
            }
            cpa_mbar_arrive(barBase + 16 * st);      // arrive full when copies land
            if (++st == NSTAGE) { st = 0; ph ^= 1; }
        }
    } else {
        // ======================= CONSUMER WARPS ======================
        const int warpM = wid >> 1;   // 0..1 (64 oc rows each)
        const int warpN = wid & 1;    // 0..1 (64 px cols each)
        // A (x4): row = warpM*64 + m*16 + (lane&15); col16B = (lane>>4)
        const uint32_t aRowB = ((uint32_t)warpM * 64u + (lane & 15)) * 128u
                               + ((lane >> 4) * 16u);
        // B (x4, 2 n-tiles per load): row = warpN*64 + np*16 + (lane>>4)*8 + (lane&7)
        const uint32_t bRowB = ((uint32_t)warpN * 64u + (lane >> 4) * 8u + (lane & 7)) * 128u
                               + (((lane >> 3) & 1) * 16u);

        float acc[4][8][4];
#pragma unroll
        for (int m = 0; m < 4; ++m)
#pragma unroll
            for (int n = 0; n < 8; ++n)
#pragma unroll
                for (int i = 0; i < 4; ++i) acc[m][n][i] = 0.f;

        int st = 0, ph = 0;
#pragma unroll 1
        for (int s = 0; s < 36; ++s) {
            MBARRIER_WAIT_PARITY(barBase + 16 * st, ph);   // wait full (acquire)
            const uint32_t stg = sb + (uint32_t)st * STAGE_BYTES;
#pragma unroll
            for (int kk = 0; kk < 4; ++kk) {
                uint32_t A[4][4], B[4][4];
#pragma unroll
                for (int np = 0; np < 4; ++np) {
                    const uint32_t off = swz(bRowB + (uint32_t)np * 2048u + (uint32_t)kk * 32u);
                    ldsm_x4(B[np][0], B[np][1], B[np][2], B[np][3], stg + 16384u + off);
                }
#pragma unroll
                for (int m = 0; m < 4; ++m) {
                    const uint32_t off = swz(aRowB + (uint32_t)m * 2048u + (uint32_t)kk * 32u);
                    ldsm_x4(A[m][0], A[m][1], A[m][2], A[m][3], stg + off);
                }
#pragma unroll
                for (int m = 0; m < 4; ++m)
#pragma unroll
                    for (int n = 0; n < 8; ++n)
                        mma_fp16(acc[m][n], A[m], &B[n >> 1][(n & 1) * 2]);
            }
            if (lane == 0) MBARRIER_ARRIVE(barBase + 16 * st + 8);   // arrive empty
            if (++st == NSTAGE) { st = 0; ph ^= 1; }
        }

        // ---- epilogue ----
        const int r0 = mt * 128 + warpM * 64 + (lane >> 2);
        const int xc = warpN * 64 + (lane & 3) * 2;
#pragma unroll
        for (int m = 0; m < 4; ++m) {
#pragma unroll
            for (int n = 0; n < 8; ++n) {
                float* p0 = out + (((size_t)(b * CC + r0 + m * 16) * HH + y) * WW) + xc + n * 8;
                float* p1 = p0 + (size_t)8 * HH * WW;
                *(float2*)p0 = make_float2(acc[m][n][0], acc[m][n][1]);
                *(float2*)p1 = make_float2(acc[m][n][2], acc[m][n][3]);
            }
        }
    }
}

// ---------------------------------------------------------------------------
extern "C" void kernel_launch(void* const* d_in, const int* in_sizes, int n_in,
                              void* d_out, int out_size) {
    const float* fea    = (const float*)d_in[0];
    const float* nf     = (const float*)d_in[1];
    const float* mw     = (const float*)d_in[2];
    const float* mb     = (const float*)d_in[3];
    const float* weight = (const float*)d_in[4];
    float* out = (float*)d_out;

    cudaFuncSetAttribute(gemm_kernel, cudaFuncAttributeMaxDynamicSharedMemorySize, SMEM_TOTAL);

    style_kernel<<<BB, CC>>>(nf, mw, mb);
    modw_kernel<<<dim3(CC, BB), CC>>>(weight);
    tsplit_kernel<<<dim3(HH, BB), 256>>>(fea);
    gemm_kernel<<<dim3(HH, 2, BB), 160, SMEM_TOTAL>>>(out);
}